// round 16
// baseline (speedup 1.0000x reference)
#include <cuda_runtime.h>
#include <math.h>

#define N_NODES 8192
#define E_EDGES 262144
#define IN_CH   256
#define HEADS   8
#define CPH     32
#define HC      256                    // HEADS*CPH
#define VLEN    (N_NODES * HC)         // 2097152
#define NEG_SLOPE 0.2f
#define ELL_W   128                    // max degree slot count (mean 32, max ~57)
#define NW      (N_NODES * ELL_W)      // one alpha plane

// ---------------- device scratch (no allocations allowed) ----------------
__device__ float g_xh[N_NODES * HC];        // projected features [n, h*c]
__device__ float g_asrc[N_NODES * HEADS];
__device__ float g_adst[N_NODES * HEADS];
__device__ int   g_fill[N_NODES];
__device__ int   g_ell[NW];                 // ELL adjacency (src ids per dst)
__device__ float g_alpha[HEADS * NW];       // per-head ELL alpha planes
__device__ float g_denom[N_NODES * HEADS];  // softmax denominators (atomic)
__device__ float g_v[VLEN];                 // agg + bias, flattened
__device__ float g_y[CPH];                  // output logits (atomic accum)

// ---------------- packed f32x2 helpers (Blackwell FFMA2) ----------------
__device__ __forceinline__ unsigned long long pk2(float lo, float hi) {
    unsigned long long r;
    asm("mov.b64 %0, {%1, %2};" : "=l"(r) : "f"(lo), "f"(hi));
    return r;
}
__device__ __forceinline__ void upk2(unsigned long long v, float& lo, float& hi) {
    asm("mov.b64 {%0, %1}, %2;" : "=f"(lo), "=f"(hi) : "l"(v));
}
__device__ __forceinline__ void fma2(unsigned long long& d,
                                     unsigned long long a, unsigned long long b) {
    asm("fma.rn.f32x2 %0, %1, %2, %3;" : "=l"(d) : "l"(a), "l"(b), "l"(d));
}

__device__ __forceinline__ float leaky_exp(float v) {
    v = v > 0.f ? v : NEG_SLOPE * v;
    return __expf(v);
}

// ---------------- K0: init scratch (self loop pre-seeded in ELL slot 0) ----------------
__global__ void k_zero() {
    int i = blockIdx.x * blockDim.x + threadIdx.x;
    if (i < N_NODES) {
        g_fill[i] = 1;
        g_ell[i * ELL_W] = i;
#pragma unroll
        for (int h = 0; h < HEADS; h++) g_denom[i * HEADS + h] = 0.f;
    }
    if (i < CPH) g_y[i] = 0.f;
}

// ---------------- K1: GEMM xh = x @ lin_w^T, attvec fused into epilogue ----------------
__global__ __launch_bounds__(256) void k_gemm(const float* __restrict__ x,
                                              const float* __restrict__ w,
                                              const float* __restrict__ att_src,
                                              const float* __restrict__ att_dst) {
    __shared__ __align__(16) float As[16 * 68];   // [k][m], stride 68
    __shared__ __align__(16) float Bs[16 * 68];   // [k][n]
    int tid = threadIdx.x;
    int tx = tid & 15, ty = tid >> 4;
    int m0 = blockIdx.x * 64;
    int n0 = blockIdx.y * 64;

    unsigned long long acc2[4][2];
#pragma unroll
    for (int i = 0; i < 4; i++) { acc2[i][0] = 0ull; acc2[i][1] = 0ull; }

    int lrow = tid >> 2;            // 0..63 (m or n within tile)
    int lcol = (tid & 3) * 4;       // k sub-offset 0,4,8,12

    for (int k0 = 0; k0 < IN_CH; k0 += 16) {
        float4 av = *(const float4*)&x[(size_t)(m0 + lrow) * IN_CH + k0 + lcol];
        float4 bv = *(const float4*)&w[(size_t)(n0 + lrow) * IN_CH + k0 + lcol];
        As[(lcol + 0) * 68 + lrow] = av.x; As[(lcol + 1) * 68 + lrow] = av.y;
        As[(lcol + 2) * 68 + lrow] = av.z; As[(lcol + 3) * 68 + lrow] = av.w;
        Bs[(lcol + 0) * 68 + lrow] = bv.x; Bs[(lcol + 1) * 68 + lrow] = bv.y;
        Bs[(lcol + 2) * 68 + lrow] = bv.z; Bs[(lcol + 3) * 68 + lrow] = bv.w;
        __syncthreads();
#pragma unroll
        for (int k = 0; k < 16; k++) {
            float4 a4 = *(const float4*)&As[k * 68 + ty * 4];
            float4 b4 = *(const float4*)&Bs[k * 68 + tx * 4];
            unsigned long long b2lo = pk2(b4.x, b4.y);
            unsigned long long b2hi = pk2(b4.z, b4.w);
            unsigned long long a0 = pk2(a4.x, a4.x);
            unsigned long long a1 = pk2(a4.y, a4.y);
            unsigned long long a2 = pk2(a4.z, a4.z);
            unsigned long long a3 = pk2(a4.w, a4.w);
            fma2(acc2[0][0], a0, b2lo); fma2(acc2[0][1], a0, b2hi);
            fma2(acc2[1][0], a1, b2lo); fma2(acc2[1][1], a1, b2hi);
            fma2(acc2[2][0], a2, b2lo); fma2(acc2[2][1], a2, b2hi);
            fma2(acc2[3][0], a3, b2lo); fma2(acc2[3][1], a3, b2hi);
        }
        __syncthreads();
    }

    // epilogue: write xh tile + fused attention scalars
    int h = (n0 >> 5) + (tx >> 3);                 // global head for this thread's cols
    float4 as4 = ((const float4*)att_src)[h * 8 + (tx & 7)];
    float4 ad4 = ((const float4*)att_dst)[h * 8 + (tx & 7)];
#pragma unroll
    for (int i = 0; i < 4; i++) {
        float4 o;
        upk2(acc2[i][0], o.x, o.y);
        upk2(acc2[i][1], o.z, o.w);
        *(float4*)&g_xh[(size_t)(m0 + ty * 4 + i) * HC + n0 + tx * 4] = o;

        float s1 = o.x * as4.x + o.y * as4.y + o.z * as4.z + o.w * as4.w;
        float s2 = o.x * ad4.x + o.y * ad4.y + o.z * ad4.z + o.w * ad4.w;
#pragma unroll
        for (int off = 4; off; off >>= 1) {
            s1 += __shfl_down_sync(0xffffffffu, s1, off);
            s2 += __shfl_down_sync(0xffffffffu, s2, off);
        }
        if ((tx & 7) == 0) {
            int m = m0 + ty * 4 + i;
            g_asrc[m * HEADS + h] = s1;
            g_adst[m * HEADS + h] = s2;
        }
    }
}

// ---------------- K3: ELL scatter + per-edge alpha precompute ----------------
// Edge blocks: thread per edge computes slot, 8 head-alphas (asrc/adst rows are
// contiguous 32B -> cheap loads), writes alpha into per-head ELL planes and
// accumulates denominators with fire-and-forget atomics. Extra blocks handle
// self loops (slot 0 pre-seeded).
#define SCAT_EDGE_BLOCKS (E_EDGES / 256)   // 1024
__global__ __launch_bounds__(256) void k_scatter(const int* __restrict__ ei) {
    const float4* a4 = (const float4*)g_asrc;
    const float4* b4 = (const float4*)g_adst;
    int src, dst, slot;
    if (blockIdx.x < SCAT_EDGE_BLOCKS) {
        int e = blockIdx.x * 256 + threadIdx.x;
        src = ei[e];
        dst = ei[E_EDGES + e];
        slot = atomicAdd(&g_fill[dst], 1);
        g_ell[dst * ELL_W + slot] = src;
    } else {
        int i = (blockIdx.x - SCAT_EDGE_BLOCKS) * 256 + threadIdx.x;
        src = i; dst = i; slot = 0;            // self loop (ell pre-seeded)
    }
    float4 s0 = a4[src * 2], s1 = a4[src * 2 + 1];
    float4 d0 = b4[dst * 2], d1 = b4[dst * 2 + 1];
    float al[HEADS];
    al[0] = leaky_exp(s0.x + d0.x);
    al[1] = leaky_exp(s0.y + d0.y);
    al[2] = leaky_exp(s0.z + d0.z);
    al[3] = leaky_exp(s0.w + d0.w);
    al[4] = leaky_exp(s1.x + d1.x);
    al[5] = leaky_exp(s1.y + d1.y);
    al[6] = leaky_exp(s1.z + d1.z);
    al[7] = leaky_exp(s1.w + d1.w);
    int idx = dst * ELL_W + slot;
#pragma unroll
    for (int h = 0; h < HEADS; h++) {
        g_alpha[h * NW + idx] = al[h];
        atomicAdd(&g_denom[dst * HEADS + h], al[h]);
    }
}

// ---------------- K4: aggregation, warp-per-(node,head), all loads coalesced ----------------
__global__ __launch_bounds__(256) void k_agg(const float* __restrict__ bias) {
    int i = blockIdx.x;
    int lane = threadIdx.x & 31;
    int h = threadIdx.x >> 5;
    int beg = i * ELL_W, end = beg + g_fill[i];
    const float* __restrict__ xh = g_xh;
    const float* __restrict__ aph = g_alpha + h * NW;
    int off = h * CPH + lane;

    float acc = 0.f;

    for (int base = beg; base < end; base += 32) {
        int e = base + lane;
        int j = 0;
        float alpha = 0.f;
        if (e < end) {
            j = g_ell[e];        // coalesced
            alpha = aph[e];      // coalesced
        }
        int nn = min(32, end - base);
        int t = 0;
        for (; t + 8 <= nn; t += 8) {
            float a0 = __shfl_sync(0xffffffffu, alpha, t + 0);
            float a1 = __shfl_sync(0xffffffffu, alpha, t + 1);
            float a2 = __shfl_sync(0xffffffffu, alpha, t + 2);
            float a3 = __shfl_sync(0xffffffffu, alpha, t + 3);
            float a4 = __shfl_sync(0xffffffffu, alpha, t + 4);
            float a5 = __shfl_sync(0xffffffffu, alpha, t + 5);
            float a6 = __shfl_sync(0xffffffffu, alpha, t + 6);
            float a7 = __shfl_sync(0xffffffffu, alpha, t + 7);
            int j0 = __shfl_sync(0xffffffffu, j, t + 0);
            int j1 = __shfl_sync(0xffffffffu, j, t + 1);
            int j2 = __shfl_sync(0xffffffffu, j, t + 2);
            int j3 = __shfl_sync(0xffffffffu, j, t + 3);
            int j4 = __shfl_sync(0xffffffffu, j, t + 4);
            int j5 = __shfl_sync(0xffffffffu, j, t + 5);
            int j6 = __shfl_sync(0xffffffffu, j, t + 6);
            int j7 = __shfl_sync(0xffffffffu, j, t + 7);
            float x0 = xh[(size_t)j0 * HC + off];
            float x1 = xh[(size_t)j1 * HC + off];
            float x2 = xh[(size_t)j2 * HC + off];
            float x3 = xh[(size_t)j3 * HC + off];
            float x4 = xh[(size_t)j4 * HC + off];
            float x5 = xh[(size_t)j5 * HC + off];
            float x6 = xh[(size_t)j6 * HC + off];
            float x7 = xh[(size_t)j7 * HC + off];
            acc = fmaf(a0, x0, acc); acc = fmaf(a1, x1, acc);
            acc = fmaf(a2, x2, acc); acc = fmaf(a3, x3, acc);
            acc = fmaf(a4, x4, acc); acc = fmaf(a5, x5, acc);
            acc = fmaf(a6, x6, acc); acc = fmaf(a7, x7, acc);
        }
        for (; t < nn; t++) {
            float a = __shfl_sync(0xffffffffu, alpha, t);
            int jj  = __shfl_sync(0xffffffffu, j, t);
            acc = fmaf(a, xh[(size_t)jj * HC + off], acc);
        }
    }
    float dinv = 1.f / g_denom[i * HEADS + h];
    g_v[(size_t)i * HC + off] = fmaf(acc, dinv, bias[off]);
}

// ---------------- K5: matvec, warp owns 4 channels exclusively ----------------
#define CHUNK 2048
__global__ __launch_bounds__(256) void k_matvec(const float* __restrict__ out_w) {
    __shared__ __align__(16) float sv[CHUNK];
    int k0 = blockIdx.x * CHUNK;
    int tid = threadIdx.x;
    int lane = tid & 31, wid = tid >> 5;
    const float4* v4 = (const float4*)&g_v[k0];
    float4* sv4 = (float4*)sv;
#pragma unroll
    for (int i = 0; i < CHUNK / 4 / 256; i++) sv4[tid + i * 256] = v4[tid + i * 256];
    __syncthreads();
    const float4* svc = (const float4*)sv;
#pragma unroll
    for (int cc = 0; cc < 4; cc++) {
        int c = wid * 4 + cc;
        const float4* w4 = (const float4*)(out_w + (size_t)c * VLEN + k0);
        float p0 = 0.f, p1 = 0.f;
#pragma unroll
        for (int i = 0; i < 8; i++) {      // 16 float4 per lane, 2-way ILP
            float4 w0 = w4[lane + (2 * i + 0) * 32];
            float4 w1 = w4[lane + (2 * i + 1) * 32];
            float4 v0 = svc[lane + (2 * i + 0) * 32];
            float4 v1 = svc[lane + (2 * i + 1) * 32];
            p0 = fmaf(w0.x, v0.x, p0); p0 = fmaf(w0.y, v0.y, p0);
            p0 = fmaf(w0.z, v0.z, p0); p0 = fmaf(w0.w, v0.w, p0);
            p1 = fmaf(w1.x, v1.x, p1); p1 = fmaf(w1.y, v1.y, p1);
            p1 = fmaf(w1.z, v1.z, p1); p1 = fmaf(w1.w, v1.w, p1);
        }
        float p = p0 + p1;
#pragma unroll
        for (int off = 16; off; off >>= 1) p += __shfl_down_sync(0xffffffffu, p, off);
        if (lane == 0) atomicAdd(&g_y[c], p);
    }
}

// ---------------- K6: softmax over 32 logits ----------------
__global__ void k_softmax(const float* __restrict__ out_b, float* __restrict__ out) {
    int t = threadIdx.x;  // 32 threads
    float v = g_y[t] + out_b[t];
    float mx = v;
#pragma unroll
    for (int off = 16; off; off >>= 1) mx = fmaxf(mx, __shfl_xor_sync(0xffffffffu, mx, off));
    float e = expf(v - mx);
    float ssum = e;
#pragma unroll
    for (int off = 16; off; off >>= 1) ssum += __shfl_xor_sync(0xffffffffu, ssum, off);
    out[t] = e / ssum;
}

// ---------------- launch ----------------
extern "C" void kernel_launch(void* const* d_in, const int* in_sizes, int n_in,
                              void* d_out, int out_size) {
    const float* x       = (const float*)d_in[0];
    const int*   ei      = (const int*)d_in[1];
    const float* lin_w   = (const float*)d_in[2];
    const float* att_src = (const float*)d_in[3];
    const float* att_dst = (const float*)d_in[4];
    const float* bias    = (const float*)d_in[5];
    const float* out_w   = (const float*)d_in[6];
    const float* out_b   = (const float*)d_in[7];
    float* out = (float*)d_out;

    k_zero<<<(N_NODES + 255) / 256, 256>>>();
    k_gemm<<<dim3(N_NODES / 64, HC / 64), 256>>>(x, lin_w, att_src, att_dst);
    k_scatter<<<SCAT_EDGE_BLOCKS + N_NODES / 256, 256>>>(ei);
    k_agg<<<N_NODES, 256>>>(bias);
    k_matvec<<<VLEN / CHUNK, 256>>>(out_w);
    k_softmax<<<1, 32>>>(out_b, out);
}